// round 1
// baseline (speedup 1.0000x reference)
#include <cuda_runtime.h>
#include <math_constants.h>

#define BN 4
#define TT 512
#define SS 512
#define IND 512
#define MD 256

// Scratch (allocation-free rule: __device__ globals)
__device__ float g_wq[BN * TT * MD];   // [b*T+t][d]
__device__ float g_uht[BN * MD * SS];  // [b][d][s]  (transposed uh)
__device__ float g_c[BN * TT * MD];    // [b*T+t][m]

__device__ __forceinline__ float tanhap(float x) {
    float y;
    asm("tanh.approx.f32 %0, %1;" : "=f"(y) : "f"(x));
    return y;
}

// ---------------------------------------------------------------------------
// proj_kernel: z=0 -> g_wq = inputs @ Wq^T            (M=2048, N=256, K=512)
//              z=1 -> g_uht[b][n][s] = mems @ Wc^T+bc (M=2048, N=256, K=256)
// 128x64 block tile, 8x4 per thread, TK=8, register prefetch.
// ---------------------------------------------------------------------------
__global__ __launch_bounds__(256) void proj_kernel(
    const float* __restrict__ inputs, const float* __restrict__ mems,
    const float* __restrict__ Wq, const float* __restrict__ Wc,
    const float* __restrict__ bc)
{
    const int z = blockIdx.z;
    const float* A  = z ? mems : inputs;
    const float* Bm = z ? Wc : Wq;
    const int K = z ? MD : IND;

    __shared__ float As[8][132];
    __shared__ float Bs[8][68];

    const int tid = threadIdx.x;
    const int bm = blockIdx.y * 128;
    const int bn = blockIdx.x * 64;
    const int lrA = tid >> 1;
    const int lcA = (tid & 1) * 4;
    const int tx = tid & 15, ty = tid >> 4;
    const int n0 = tx * 4, m0 = ty * 8;

    float acc[8][4];
#pragma unroll
    for (int i = 0; i < 8; i++)
#pragma unroll
        for (int j = 0; j < 4; j++) acc[i][j] = 0.f;

    float4 a4 = *(const float4*)(A + (bm + lrA) * K + lcA);
    float4 b4 = make_float4(0.f, 0.f, 0.f, 0.f);
    if (tid < 128) b4 = *(const float4*)(Bm + (bn + lrA) * K + lcA);

    for (int k0 = 0; k0 < K; k0 += 8) {
        As[lcA + 0][lrA] = a4.x; As[lcA + 1][lrA] = a4.y;
        As[lcA + 2][lrA] = a4.z; As[lcA + 3][lrA] = a4.w;
        if (tid < 128) {
            Bs[lcA + 0][lrA] = b4.x; Bs[lcA + 1][lrA] = b4.y;
            Bs[lcA + 2][lrA] = b4.z; Bs[lcA + 3][lrA] = b4.w;
        }
        __syncthreads();
        const int kn = k0 + 8;
        if (kn < K) {
            a4 = *(const float4*)(A + (bm + lrA) * K + kn + lcA);
            if (tid < 128) b4 = *(const float4*)(Bm + (bn + lrA) * K + kn + lcA);
        }
#pragma unroll
        for (int kk = 0; kk < 8; kk++) {
            float4 x0 = *(const float4*)&As[kk][m0];
            float4 x1 = *(const float4*)&As[kk][m0 + 4];
            float4 y  = *(const float4*)&Bs[kk][n0];
            float am[8] = {x0.x, x0.y, x0.z, x0.w, x1.x, x1.y, x1.z, x1.w};
            float bb[4] = {y.x, y.y, y.z, y.w};
#pragma unroll
            for (int i = 0; i < 8; i++)
#pragma unroll
                for (int j = 0; j < 4; j++) acc[i][j] += am[i] * bb[j];
        }
        __syncthreads();
    }

    if (z == 0) {
#pragma unroll
        for (int i = 0; i < 8; i++) {
            float4 r = make_float4(acc[i][0], acc[i][1], acc[i][2], acc[i][3]);
            *(float4*)&g_wq[(bm + m0 + i) * MD + bn + n0] = r;
        }
    } else {
        float bb[4];
#pragma unroll
        for (int j = 0; j < 4; j++) bb[j] = bc[bn + n0 + j];
#pragma unroll
        for (int i = 0; i < 8; i++) {
            const int m = bm + m0 + i;
            const int b = m >> 9;
            const int s = m & 511;
#pragma unroll
            for (int j = 0; j < 4; j++)
                g_uht[b * (MD * SS) + (bn + n0 + j) * SS + s] = acc[i][j] + bb[j];
        }
    }
}

// ---------------------------------------------------------------------------
// attn_kernel: one block per (b, 16-t tile). Phases:
//   1: align[t][s] = sum_d v_d * tanh(wq[t][d] + uh[s][d])   (MUFU-bound)
//   2: masked softmax over s
//   3: c[t][m] = sum_s p[t][s] * mems[b][s][m]
// Dynamic smem: uh/mems chunk 128KB | wq 16KB | v 1KB | align 32KB
// ---------------------------------------------------------------------------
__global__ __launch_bounds__(256) void attn_kernel(
    const float* __restrict__ mems, const int* __restrict__ mem_masks,
    const float* __restrict__ v, float* __restrict__ align_out)
{
    extern __shared__ float sh[];
    float* uh_sh = sh;                    // [256][128] (phase3: [128][256])
    float* wq_sh = sh + 256 * 128;        // [16][256]
    float* v_sh  = wq_sh + 16 * 256;      // [256]
    float* al_sh = v_sh + 256;            // [16][512]

    const int tid = threadIdx.x;
    const int lane = tid & 31;
    const int warp = tid >> 5;
    const int b = blockIdx.x >> 5;
    const int t0 = (blockIdx.x & 31) * 16;
    const int len = mem_masks[b];
    const float NEG = -CUDART_INF_F;

    // load wq tile, v, init align to -inf
    {
        const float* src = g_wq + (b * TT + t0) * MD;
        for (int i = tid; i < (16 * 256) / 4; i += 256)
            *(float4*)&wq_sh[i * 4] = *(const float4*)&src[i * 4];
        if (tid < 64)
            *(float4*)&v_sh[tid * 4] = *(const float4*)&v[tid * 4];
        for (int i = tid; i < 16 * 512; i += 256) al_sh[i] = NEG;
    }

    const int nch = (len + 127) >> 7;

    // ---------- Phase 1: align ----------
    for (int c = 0; c < nch; c++) {
        __syncthreads();
        {   // load uh chunk [256 d][128 s] from g_uht (coalesced per warp)
            const float* src = g_uht + b * (MD * SS) + c * 128;
            for (int i = tid; i < 256 * 32; i += 256) {
                const int d = i >> 5, g = i & 31;
                *(float4*)&uh_sh[d * 128 + g * 4] =
                    *(const float4*)&src[d * SS + g * 4];
            }
        }
        __syncthreads();

        const int ta = warp * 2;
        const float* wq0 = wq_sh + ta * 256;
        const float* wq1 = wq0 + 256;
        const int sl = lane * 4;
        float4 a0 = make_float4(0.f, 0.f, 0.f, 0.f);
        float4 a1 = make_float4(0.f, 0.f, 0.f, 0.f);
#pragma unroll 4
        for (int d = 0; d < 256; d++) {
            float4 u = *(float4*)&uh_sh[d * 128 + sl];
            float w0 = wq0[d], w1 = wq1[d], vd = v_sh[d];
            a0.x += vd * tanhap(u.x + w0);
            a0.y += vd * tanhap(u.y + w0);
            a0.z += vd * tanhap(u.z + w0);
            a0.w += vd * tanhap(u.w + w0);
            a1.x += vd * tanhap(u.x + w1);
            a1.y += vd * tanhap(u.y + w1);
            a1.z += vd * tanhap(u.z + w1);
            a1.w += vd * tanhap(u.w + w1);
        }
        const int sg = c * 128 + sl;
        float4 r0, r1;
        r0.x = (sg + 0 < len) ? a0.x : NEG;
        r0.y = (sg + 1 < len) ? a0.y : NEG;
        r0.z = (sg + 2 < len) ? a0.z : NEG;
        r0.w = (sg + 3 < len) ? a0.w : NEG;
        r1.x = (sg + 0 < len) ? a1.x : NEG;
        r1.y = (sg + 1 < len) ? a1.y : NEG;
        r1.z = (sg + 2 < len) ? a1.z : NEG;
        r1.w = (sg + 3 < len) ? a1.w : NEG;
        *(float4*)&al_sh[ta * 512 + sg] = r0;
        *(float4*)&al_sh[(ta + 1) * 512 + sg] = r1;
    }
    __syncthreads();

    // ---------- Phase 2: masked softmax (warp per 2 rows) ----------
    for (int r = 0; r < 2; r++) {
        const int t = warp * 2 + r;
        float* row = al_sh + t * 512;
        float mx = NEG;
#pragma unroll
        for (int k = 0; k < 16; k++) mx = fmaxf(mx, row[lane + k * 32]);
#pragma unroll
        for (int o = 16; o; o >>= 1) mx = fmaxf(mx, __shfl_xor_sync(~0u, mx, o));
        float e[16];
        float sum = 0.f;
#pragma unroll
        for (int k = 0; k < 16; k++) {
            const int s = lane + k * 32;
            const float val = (s < len) ? __expf(row[s] - mx) : 0.f;
            e[k] = val;
            sum += val;
        }
#pragma unroll
        for (int o = 16; o; o >>= 1) sum += __shfl_xor_sync(~0u, sum, o);
        const float inv = 1.0f / sum;
#pragma unroll
        for (int k = 0; k < 16; k++) {
            const int s = lane + k * 32;
            const float p = e[k] * inv;
            row[s] = p;
            if (align_out) align_out[(b * TT + t0 + t) * SS + s] = p;
        }
    }

    // ---------- Phase 3: context c = P @ mems ----------
    float cc[4][4];
#pragma unroll
    for (int i = 0; i < 4; i++)
#pragma unroll
        for (int j = 0; j < 4; j++) cc[i][j] = 0.f;

    const int tq = (tid >> 6) * 4;
    const int m0 = (tid & 63) * 4;

    for (int c = 0; c < nch; c++) {
        __syncthreads();
        {   // load mems chunk [128 s][256 m] (fully contiguous)
            const float* src = mems + b * (SS * MD) + c * 128 * MD;
            for (int i = tid; i < (128 * 256) / 4; i += 256)
                *(float4*)&uh_sh[i * 4] = *(const float4*)&src[i * 4];
        }
        __syncthreads();
#pragma unroll 2
        for (int s2 = 0; s2 < 128; s2++) {
            float4 mm = *(float4*)&uh_sh[s2 * 256 + m0];
            const int s = c * 128 + s2;
            const float p0 = al_sh[(tq + 0) * 512 + s];
            const float p1 = al_sh[(tq + 1) * 512 + s];
            const float p2 = al_sh[(tq + 2) * 512 + s];
            const float p3 = al_sh[(tq + 3) * 512 + s];
            cc[0][0] += p0 * mm.x; cc[0][1] += p0 * mm.y;
            cc[0][2] += p0 * mm.z; cc[0][3] += p0 * mm.w;
            cc[1][0] += p1 * mm.x; cc[1][1] += p1 * mm.y;
            cc[1][2] += p1 * mm.z; cc[1][3] += p1 * mm.w;
            cc[2][0] += p2 * mm.x; cc[2][1] += p2 * mm.y;
            cc[2][2] += p2 * mm.z; cc[2][3] += p2 * mm.w;
            cc[3][0] += p3 * mm.x; cc[3][1] += p3 * mm.y;
            cc[3][2] += p3 * mm.z; cc[3][3] += p3 * mm.w;
        }
    }
#pragma unroll
    for (int i = 0; i < 4; i++) {
        float4 r = make_float4(cc[i][0], cc[i][1], cc[i][2], cc[i][3]);
        *(float4*)&g_c[(b * TT + t0 + tq + i) * MD + m0] = r;
    }
}

// ---------------------------------------------------------------------------
// out_kernel: attn_h = concat(c, inputs) @ Wout^T + bout
// M=2048, N=512, K=768. Same 128x64 / 8x4 tiling.
// ---------------------------------------------------------------------------
__global__ __launch_bounds__(256) void out_kernel(
    const float* __restrict__ inputs, const float* __restrict__ Wout,
    const float* __restrict__ bout, float* __restrict__ out)
{
    __shared__ float As[8][132];
    __shared__ float Bs[8][68];

    const int tid = threadIdx.x;
    const int bm = blockIdx.y * 128;
    const int bn = blockIdx.x * 64;
    const int lrA = tid >> 1;
    const int lcA = (tid & 1) * 4;
    const int tx = tid & 15, ty = tid >> 4;
    const int n0 = tx * 4, m0 = ty * 8;

    float acc[8][4];
#pragma unroll
    for (int i = 0; i < 8; i++)
#pragma unroll
        for (int j = 0; j < 4; j++) acc[i][j] = 0.f;

    auto loadA = [&](int k0) -> float4 {
        const int k = k0 + lcA;
        if (k < 256)
            return *(const float4*)(g_c + (bm + lrA) * MD + k);
        return *(const float4*)(inputs + (bm + lrA) * IND + (k - 256));
    };

    float4 a4 = loadA(0);
    float4 b4 = make_float4(0.f, 0.f, 0.f, 0.f);
    if (tid < 128) b4 = *(const float4*)(Wout + (bn + lrA) * 768 + lcA);

    for (int k0 = 0; k0 < 768; k0 += 8) {
        As[lcA + 0][lrA] = a4.x; As[lcA + 1][lrA] = a4.y;
        As[lcA + 2][lrA] = a4.z; As[lcA + 3][lrA] = a4.w;
        if (tid < 128) {
            Bs[lcA + 0][lrA] = b4.x; Bs[lcA + 1][lrA] = b4.y;
            Bs[lcA + 2][lrA] = b4.z; Bs[lcA + 3][lrA] = b4.w;
        }
        __syncthreads();
        const int kn = k0 + 8;
        if (kn < 768) {
            a4 = loadA(kn);
            if (tid < 128) b4 = *(const float4*)(Wout + (bn + lrA) * 768 + kn + lcA);
        }
#pragma unroll
        for (int kk = 0; kk < 8; kk++) {
            float4 x0 = *(const float4*)&As[kk][m0];
            float4 x1 = *(const float4*)&As[kk][m0 + 4];
            float4 y  = *(const float4*)&Bs[kk][n0];
            float am[8] = {x0.x, x0.y, x0.z, x0.w, x1.x, x1.y, x1.z, x1.w};
            float bb[4] = {y.x, y.y, y.z, y.w};
#pragma unroll
            for (int i = 0; i < 8; i++)
#pragma unroll
                for (int j = 0; j < 4; j++) acc[i][j] += am[i] * bb[j];
        }
        __syncthreads();
    }

    float4 bias = *(const float4*)(bout + bn + n0);
#pragma unroll
    for (int i = 0; i < 8; i++) {
        float4 r = make_float4(acc[i][0] + bias.x, acc[i][1] + bias.y,
                               acc[i][2] + bias.z, acc[i][3] + bias.w);
        *(float4*)&out[(bm + m0 + i) * IND + bn + n0] = r;
    }
}

// ---------------------------------------------------------------------------
extern "C" void kernel_launch(void* const* d_in, const int* in_sizes, int n_in,
                              void* d_out, int out_size)
{
    const float* inputs    = (const float*)d_in[0];
    const float* mems      = (const float*)d_in[1];
    const int*   mem_masks = (const int*)d_in[2];
    const float* Wq        = (const float*)d_in[3];
    const float* Wc        = (const float*)d_in[4];
    const float* bc        = (const float*)d_in[5];
    const float* v         = (const float*)d_in[6];
    const float* Wout      = (const float*)d_in[7];
    const float* bout      = (const float*)d_in[8];

    float* out = (float*)d_out;
    // output = concat(attn_h [B*T*IND], align_vectors [B*T*S])
    float* align_out = (out_size >= BN * TT * IND + BN * TT * SS)
                           ? out + BN * TT * IND
                           : nullptr;

    const size_t SMEM =
        (size_t)(256 * 128 + 16 * 256 + 256 + 16 * 512) * sizeof(float);
    cudaFuncSetAttribute(attn_kernel,
                         cudaFuncAttributeMaxDynamicSharedMemorySize,
                         (int)SMEM);

    proj_kernel<<<dim3(4, 16, 2), 256>>>(inputs, mems, Wq, Wc, bc);
    attn_kernel<<<128, 256, SMEM>>>(mems, mem_masks, v, align_out);
    out_kernel<<<dim3(8, 16), 256>>>(inputs, Wout, bout, out);
}